// round 5
// baseline (speedup 1.0000x reference)
#include <cuda_runtime.h>

// GraphSAGE 2-layer, N=100000 nodes, E=1600000 edges, dims 32 -> 64 -> 32.
// Atomic-free aggregation via per-call CSR build (dst-indexed):
//   B0: zero degree counters
//   B1: count  deg[dst]++            (int atomics)
//   B2: scan   off = exscan(deg); cur = off   (single block)
//   B3: fill   adj[cur[dst]++] = src
//   K1: gather g_agg[i] = sum_{j in adj[i]} x[j]      (warp per node)
//   K2: fused MLP (thread per node): h=relu(W1l@agg+b1+W1r@x); g=W2l@h; r=W2r@h+b2
//   K3: gather out[i] = r[i] + sum_{j in adj[i]} g[j] (warp per node)
// Layer-2 projection applied BEFORE aggregation (linear commutes with sum).
// edge_index is int32 on device.

#define NN 100000
#define EE 1600000
#define D 32

__device__ int   g_deg[NN];
__device__ int   g_off[NN + 1];
__device__ int   g_cur[NN];
__device__ int   g_adj[EE];
__device__ float g_agg[NN * D];
__device__ float g_g[NN * D];

// ---------------------------------------------------------------------------
__global__ void zero_deg_kernel(int N) {
    int i = blockIdx.x * blockDim.x + threadIdx.x;
    if (i < N) g_deg[i] = 0;
}

__global__ void count_kernel(const int* __restrict__ dst, int E) {
    int e = blockIdx.x * blockDim.x + threadIdx.x;
    if (e < E) atomicAdd(&g_deg[dst[e]], 1);
}

// Single-block exclusive scan: 1024 threads, each owns a contiguous chunk.
__global__ void scan_kernel(int N) {
    __shared__ int sums[1024];
    int tid = threadIdx.x;
    int chunk = (N + 1023) / 1024;
    int start = tid * chunk;
    int end = start + chunk; if (end > N) end = N;
    int s = 0;
    for (int i = start; i < end; i++) s += g_deg[i];
    sums[tid] = s;
    __syncthreads();
    // Hillis-Steele inclusive scan
    for (int ofs = 1; ofs < 1024; ofs <<= 1) {
        int v = (tid >= ofs) ? sums[tid - ofs] : 0;
        __syncthreads();
        sums[tid] += v;
        __syncthreads();
    }
    int run = (tid == 0) ? 0 : sums[tid - 1];
    for (int i = start; i < end; i++) {
        g_off[i] = run;
        g_cur[i] = run;
        run += g_deg[i];
    }
    if (end == N) g_off[N] = run;
}

__global__ void fill_kernel(const int* __restrict__ src,
                            const int* __restrict__ dst, int E) {
    int e = blockIdx.x * blockDim.x + threadIdx.x;
    if (e >= E) return;
    int pos = atomicAdd(&g_cur[dst[e]], 1);
    g_adj[pos] = src[e];
}

// ---------------------------------------------------------------------------
// Warp per node; lane = feature. Each neighbor row read is one coalesced 128B.
__global__ void gather_x_kernel(const float* __restrict__ x, int N) {
    int lane = threadIdx.x & 31;
    int node = (blockIdx.x * blockDim.x + threadIdx.x) >> 5;
    if (node >= N) return;
    int j  = g_off[node];
    int j1 = g_off[node + 1];
    float acc0 = 0.f, acc1 = 0.f;
    for (; j + 1 < j1; j += 2) {
        int sA = __ldg(&g_adj[j]);
        int sB = __ldg(&g_adj[j + 1]);
        acc0 += __ldg(&x[sA * D + lane]);
        acc1 += __ldg(&x[sB * D + lane]);
    }
    if (j < j1) acc0 += __ldg(&x[__ldg(&g_adj[j]) * D + lane]);
    g_agg[node * D + lane] = acc0 + acc1;
}

__global__ void gather_g_kernel(float* __restrict__ out, int N) {
    int lane = threadIdx.x & 31;
    int node = (blockIdx.x * blockDim.x + threadIdx.x) >> 5;
    if (node >= N) return;
    int j  = g_off[node];
    int j1 = g_off[node + 1];
    float acc0 = 0.f, acc1 = 0.f;
    for (; j + 1 < j1; j += 2) {
        int sA = __ldg(&g_adj[j]);
        int sB = __ldg(&g_adj[j + 1]);
        acc0 += __ldg(&g_g[sA * D + lane]);
        acc1 += __ldg(&g_g[sB * D + lane]);
    }
    if (j < j1) acc0 += __ldg(&g_g[__ldg(&g_adj[j]) * D + lane]);
    out[node * D + lane] += acc0 + acc1;   // MLP already stored the lin_r part
}

// ---------------------------------------------------------------------------
// Thread-per-node MLP; weights broadcast from smem (identical address per warp).
__global__ void __launch_bounds__(128)
fused_mlp_kernel(const float* __restrict__ x,
                 const float* __restrict__ Wli,  // [64,32]
                 const float* __restrict__ bli,  // [64]
                 const float* __restrict__ Wri,  // [64,32]
                 const float* __restrict__ Wlo,  // [32,64]
                 const float* __restrict__ blo,  // [32]
                 const float* __restrict__ Wro,  // [32,64]
                 float* __restrict__ out,
                 int N) {
    __shared__ float4 w1l4[32 * 16];   // [k][m4]
    __shared__ float4 w1r4[32 * 16];
    __shared__ float4 w2l4[64 * 8];    // [m][o4]
    __shared__ float4 w2r4[64 * 8];
    __shared__ float4 b1s[16];
    __shared__ float4 b2s[8];

    int tid = threadIdx.x;
    {
        float* w1l = (float*)w1l4;
        float* w1r = (float*)w1r4;
        float* w2l = (float*)w2l4;
        float* w2r = (float*)w2r4;
        for (int idx = tid; idx < 2048; idx += 128) {
            int k = idx >> 6, m = idx & 63;      // stage-1: [k][m]
            w1l[k * 64 + m] = Wli[m * 32 + k];
            w1r[k * 64 + m] = Wri[m * 32 + k];
            int mm = idx >> 5, o = idx & 31;     // stage-2: [m][o]
            w2l[mm * 32 + o] = Wlo[o * 64 + mm];
            w2r[mm * 32 + o] = Wro[o * 64 + mm];
        }
        if (tid < 64) ((float*)b1s)[tid] = bli[tid];
        if (tid < 32) ((float*)b2s)[tid] = blo[tid];
    }
    __syncthreads();

    int node = blockIdx.x * 128 + tid;
    if (node >= N) return;

    float a[32], xv[32];
    {
        const float4* ar = (const float4*)&g_agg[node * D];
        const float4* xr = (const float4*)&x[node * D];
        #pragma unroll
        for (int i = 0; i < 8; i++) {
            float4 t0 = ar[i];
            a[4 * i] = t0.x; a[4 * i + 1] = t0.y; a[4 * i + 2] = t0.z; a[4 * i + 3] = t0.w;
            float4 t1 = xr[i];
            xv[4 * i] = t1.x; xv[4 * i + 1] = t1.y; xv[4 * i + 2] = t1.z; xv[4 * i + 3] = t1.w;
        }
    }

    float h[64];
    #pragma unroll
    for (int m4 = 0; m4 < 16; m4++) {
        float4 b = b1s[m4];
        h[4 * m4] = b.x; h[4 * m4 + 1] = b.y; h[4 * m4 + 2] = b.z; h[4 * m4 + 3] = b.w;
    }
    #pragma unroll
    for (int k = 0; k < 32; k++) {
        float av = a[k];
        float xx = xv[k];
        #pragma unroll
        for (int m4 = 0; m4 < 16; m4++) {
            float4 wl = w1l4[k * 16 + m4];
            float4 wr = w1r4[k * 16 + m4];
            h[4 * m4]     = fmaf(wl.x, av, fmaf(wr.x, xx, h[4 * m4]));
            h[4 * m4 + 1] = fmaf(wl.y, av, fmaf(wr.y, xx, h[4 * m4 + 1]));
            h[4 * m4 + 2] = fmaf(wl.z, av, fmaf(wr.z, xx, h[4 * m4 + 2]));
            h[4 * m4 + 3] = fmaf(wl.w, av, fmaf(wr.w, xx, h[4 * m4 + 3]));
        }
    }
    #pragma unroll
    for (int m = 0; m < 64; m++) h[m] = fmaxf(h[m], 0.0f);

    float g[32], r[32];
    #pragma unroll
    for (int o4 = 0; o4 < 8; o4++) {
        float4 b = b2s[o4];
        g[4 * o4] = 0.f; g[4 * o4 + 1] = 0.f; g[4 * o4 + 2] = 0.f; g[4 * o4 + 3] = 0.f;
        r[4 * o4] = b.x; r[4 * o4 + 1] = b.y; r[4 * o4 + 2] = b.z; r[4 * o4 + 3] = b.w;
    }
    #pragma unroll
    for (int m = 0; m < 64; m++) {
        float hv = h[m];
        #pragma unroll
        for (int o4 = 0; o4 < 8; o4++) {
            float4 wl = w2l4[m * 8 + o4];
            float4 wr = w2r4[m * 8 + o4];
            g[4 * o4]     = fmaf(wl.x, hv, g[4 * o4]);
            g[4 * o4 + 1] = fmaf(wl.y, hv, g[4 * o4 + 1]);
            g[4 * o4 + 2] = fmaf(wl.z, hv, g[4 * o4 + 2]);
            g[4 * o4 + 3] = fmaf(wl.w, hv, g[4 * o4 + 3]);
            r[4 * o4]     = fmaf(wr.x, hv, r[4 * o4]);
            r[4 * o4 + 1] = fmaf(wr.y, hv, r[4 * o4 + 1]);
            r[4 * o4 + 2] = fmaf(wr.z, hv, r[4 * o4 + 2]);
            r[4 * o4 + 3] = fmaf(wr.w, hv, r[4 * o4 + 3]);
        }
    }

    float4* gg = (float4*)&g_g[node * D];
    float4* oo = (float4*)&out[node * D];
    #pragma unroll
    for (int o4 = 0; o4 < 8; o4++) {
        gg[o4] = make_float4(g[4 * o4], g[4 * o4 + 1], g[4 * o4 + 2], g[4 * o4 + 3]);
        oo[o4] = make_float4(r[4 * o4], r[4 * o4 + 1], r[4 * o4 + 2], r[4 * o4 + 3]);
    }
}

// ---------------------------------------------------------------------------
extern "C" void kernel_launch(void* const* d_in, const int* in_sizes, int n_in,
                              void* d_out, int out_size) {
    const float* x   = (const float*)d_in[0];
    const int*   ei  = (const int*)d_in[1];
    const float* Wli = (const float*)d_in[2];
    const float* bli = (const float*)d_in[3];
    const float* Wri = (const float*)d_in[4];
    const float* Wlo = (const float*)d_in[5];
    const float* blo = (const float*)d_in[6];
    const float* Wro = (const float*)d_in[7];
    float* out = (float*)d_out;

    int N = in_sizes[0] / D;      // 100000
    int E = in_sizes[1] / 2;      // 1600000
    const int* src = ei;
    const int* dst = ei + E;

    // CSR build (per call; caching is not allowed)
    zero_deg_kernel<<<(N + 255) / 256, 256>>>(N);
    count_kernel<<<(E + 255) / 256, 256>>>(dst, E);
    scan_kernel<<<1, 1024>>>(N);
    fill_kernel<<<(E + 255) / 256, 256>>>(src, dst, E);

    // Layer 1 aggregation (gather), MLP, layer 2 aggregation (gather)
    gather_x_kernel<<<(N * 32 + 255) / 256, 256>>>(x, N);
    fused_mlp_kernel<<<(N + 127) / 128, 128>>>(x, Wli, bli, Wri, Wlo, blo, Wro, out, N);
    gather_g_kernel<<<(N * 32 + 255) / 256, 256>>>(out, N);
}

// round 6
// speedup vs baseline: 2.0092x; 2.0092x over previous
#include <cuda_runtime.h>

// GraphSAGE 2-layer, N=100000, E=1600000, dims 32 -> 64 -> 32.
//   K0: zero g_agg
//   K1: scatter  g_agg[dst] += x[src]     (8 threads/edge, v4 RED atomics)
//   K2: fused MLP, thread per node, packed fma.rn.f32x2 (FFMA2) math
//   K3: scatter  out[dst] += g_g[src]     (8 threads/edge, v4 RED atomics)
// Layer-2 projection applied BEFORE the scatter (linear commutes with sum).
// edge_index is int32 on device.

#define MAX_NODES 100000
#define D 32

typedef unsigned long long ull;

__device__ float g_agg[MAX_NODES * D];
__device__ float g_g[MAX_NODES * D];

__device__ __forceinline__ void red_add_v4(float* addr, float4 v) {
    asm volatile("red.global.add.v4.f32 [%0], {%1, %2, %3, %4};"
                 :: "l"(addr), "f"(v.x), "f"(v.y), "f"(v.z), "f"(v.w)
                 : "memory");
}

__device__ __forceinline__ ull fma2(ull a, ull b, ull c) {
    ull d;
    asm("fma.rn.f32x2 %0, %1, %2, %3;" : "=l"(d) : "l"(a), "l"(b), "l"(c));
    return d;
}
__device__ __forceinline__ ull pack2(float lo, float hi) {
    ull d;
    asm("mov.b64 %0, {%1, %2};" : "=l"(d) : "f"(lo), "f"(hi));
    return d;
}
__device__ __forceinline__ void unpack2(ull v, float& lo, float& hi) {
    asm("mov.b64 {%0, %1}, %2;" : "=f"(lo), "=f"(hi) : "l"(v));
}

// ---------------------------------------------------------------------------
__global__ void zero_agg_kernel(int n4) {
    int i = blockIdx.x * blockDim.x + threadIdx.x;
    if (i < n4) ((float4*)g_agg)[i] = make_float4(0.f, 0.f, 0.f, 0.f);
}

// ---------------------------------------------------------------------------
// 8 threads per edge; quad q handles floats [4q, 4q+4). One v4 RED per thread.
__global__ void scatter_x_kernel(const float* __restrict__ x,
                                 const int* __restrict__ src,
                                 const int* __restrict__ dst,
                                 int E) {
    int t = blockIdx.x * blockDim.x + threadIdx.x;
    int e = t >> 3;
    int q = (t & 7) << 2;
    if (e >= E) return;
    int s = __ldg(&src[e]);
    int d = __ldg(&dst[e]);
    float4 v = *(const float4*)&x[s * D + q];
    red_add_v4(&g_agg[d * D + q], v);
}

__global__ void scatter_g_kernel(float* __restrict__ out,
                                 const int* __restrict__ src,
                                 const int* __restrict__ dst,
                                 int E) {
    int t = blockIdx.x * blockDim.x + threadIdx.x;
    int e = t >> 3;
    int q = (t & 7) << 2;
    if (e >= E) return;
    int s = __ldg(&src[e]);
    int d = __ldg(&dst[e]);
    float4 v = *(const float4*)&g_g[s * D + q];
    red_add_v4(&out[d * D + q], v);
}

// ---------------------------------------------------------------------------
// Thread-per-node MLP with f32x2 packed FMA.
// smem float views (all m/o contiguous so longlong2 = 2 packed pairs):
//   W1L[k*64 + m] = Wli[m][k]   (k input dim, m hidden)
//   W2L[m*32 + o] = Wlo[o][m]   (m hidden, o output)
__global__ void __launch_bounds__(128)
fused_mlp_kernel(const float* __restrict__ x,
                 const float* __restrict__ Wli,  // [64,32]
                 const float* __restrict__ bli,  // [64]
                 const float* __restrict__ Wri,  // [64,32]
                 const float* __restrict__ Wlo,  // [32,64]
                 const float* __restrict__ blo,  // [32]
                 const float* __restrict__ Wro,  // [32,64]
                 float* __restrict__ out,
                 int N) {
    __shared__ longlong2 w1l[32][16];   // [k][m4] -> hidden 4*m4..4*m4+3
    __shared__ longlong2 w1r[32][16];
    __shared__ longlong2 w2l[64][8];    // [m][o4] -> out 4*o4..4*o4+3
    __shared__ longlong2 w2r[64][8];
    __shared__ ull b1p[32];
    __shared__ ull b2p[16];

    int tid = threadIdx.x;
    {
        float* W1L = (float*)w1l;
        float* W1R = (float*)w1r;
        float* W2L = (float*)w2l;
        float* W2R = (float*)w2r;
        for (int idx = tid; idx < 2048; idx += 128) {
            int k = idx >> 6, m = idx & 63;      // stage-1: [k][m]
            W1L[k * 64 + m] = Wli[m * 32 + k];
            W1R[k * 64 + m] = Wri[m * 32 + k];
            int mm = idx >> 5, o = idx & 31;     // stage-2: [m][o]
            W2L[mm * 32 + o] = Wlo[o * 64 + mm];
            W2R[mm * 32 + o] = Wro[o * 64 + mm];
        }
        if (tid < 64) ((float*)b1p)[tid] = bli[tid];
        if (tid < 32) ((float*)b2p)[tid] = blo[tid];
    }
    __syncthreads();

    int node = blockIdx.x * 128 + tid;
    if (node >= N) return;

    // Load this node's agg and x rows.
    float a[32], xv[32];
    {
        const float4* ar = (const float4*)&g_agg[node * D];
        const float4* xr = (const float4*)&x[node * D];
        #pragma unroll
        for (int i = 0; i < 8; i++) {
            float4 t0 = ar[i];
            a[4 * i] = t0.x; a[4 * i + 1] = t0.y; a[4 * i + 2] = t0.z; a[4 * i + 3] = t0.w;
            float4 t1 = xr[i];
            xv[4 * i] = t1.x; xv[4 * i + 1] = t1.y; xv[4 * i + 2] = t1.z; xv[4 * i + 3] = t1.w;
        }
    }

    // Stage 1: h2[32] (pairs) = b1 + W1L@a + W1R@x, packed.
    ull h2[32];
    #pragma unroll
    for (int m2 = 0; m2 < 32; m2++) h2[m2] = b1p[m2];

    #pragma unroll
    for (int k = 0; k < 32; k++) {
        ull av2 = pack2(a[k], a[k]);
        ull xx2 = pack2(xv[k], xv[k]);
        #pragma unroll
        for (int q = 0; q < 16; q++) {
            longlong2 wl = w1l[k][q];
            longlong2 wr = w1r[k][q];
            h2[2 * q]     = fma2((ull)wl.x, av2, h2[2 * q]);
            h2[2 * q + 1] = fma2((ull)wl.y, av2, h2[2 * q + 1]);
            h2[2 * q]     = fma2((ull)wr.x, xx2, h2[2 * q]);
            h2[2 * q + 1] = fma2((ull)wr.y, xx2, h2[2 * q + 1]);
        }
    }

    // ReLU (scalar unpack/repack; h lives as scalars for stage-2 broadcast)
    float hs[64];
    #pragma unroll
    for (int m2 = 0; m2 < 32; m2++) {
        float lo, hi;
        unpack2(h2[m2], lo, hi);
        hs[2 * m2]     = fmaxf(lo, 0.0f);
        hs[2 * m2 + 1] = fmaxf(hi, 0.0f);
    }

    // Stage 2: g2 = W2L@h ; r2 = b2 + W2R@h, packed.
    ull g2[16], r2[16];
    #pragma unroll
    for (int o2 = 0; o2 < 16; o2++) { g2[o2] = 0ull; r2[o2] = b2p[o2]; }

    #pragma unroll
    for (int m = 0; m < 64; m++) {
        ull hv2 = pack2(hs[m], hs[m]);
        #pragma unroll
        for (int q = 0; q < 8; q++) {
            longlong2 wl = w2l[m][q];
            longlong2 wr = w2r[m][q];
            g2[2 * q]     = fma2((ull)wl.x, hv2, g2[2 * q]);
            g2[2 * q + 1] = fma2((ull)wl.y, hv2, g2[2 * q + 1]);
            r2[2 * q]     = fma2((ull)wr.x, hv2, r2[2 * q]);
            r2[2 * q + 1] = fma2((ull)wr.y, hv2, r2[2 * q + 1]);
        }
    }

    ull* gg = (ull*)&g_g[node * D];
    ull* oo = (ull*)&out[node * D];
    #pragma unroll
    for (int o2 = 0; o2 < 16; o2++) {
        gg[o2] = g2[o2];
        oo[o2] = r2[o2];
    }
}

// ---------------------------------------------------------------------------
extern "C" void kernel_launch(void* const* d_in, const int* in_sizes, int n_in,
                              void* d_out, int out_size) {
    const float* x   = (const float*)d_in[0];
    const int*   ei  = (const int*)d_in[1];
    const float* Wli = (const float*)d_in[2];
    const float* bli = (const float*)d_in[3];
    const float* Wri = (const float*)d_in[4];
    const float* Wlo = (const float*)d_in[5];
    const float* blo = (const float*)d_in[6];
    const float* Wro = (const float*)d_in[7];
    float* out = (float*)d_out;

    int N = in_sizes[0] / D;      // 100000
    int E = in_sizes[1] / 2;      // 1600000
    const int* src = ei;
    const int* dst = ei + E;

    {   // K0: zero aggregation buffer
        int n4 = N * D / 4;
        zero_agg_kernel<<<(n4 + 255) / 256, 256>>>(n4);
    }
    {   // K1: scatter x into g_agg
        int blocks = (E + 31) / 32;
        scatter_x_kernel<<<blocks, 256>>>(x, src, dst, E);
    }
    {   // K2: fused node-wise MLP (thread per node, FFMA2)
        fused_mlp_kernel<<<(N + 127) / 128, 128>>>(x, Wli, bli, Wri, Wlo, blo, Wro, out, N);
    }
    {   // K3: scatter g into out
        int blocks = (E + 31) / 32;
        scatter_g_kernel<<<blocks, 256>>>(out, src, dst, E);
    }
}